// round 7
// baseline (speedup 1.0000x reference)
#include <cuda_runtime.h>
#include <math.h>

// Problem shape (fixed by the reference)
#define B 32
#define S 4096
#define H 768            // 768 floats = 6 float4 per lane across a warp
#define CHUNKS 32        // CTAs per batch
#define WARPS 8          // warps per CTA
#define ROWS_PER_WARP (S / CHUNKS / WARPS)   // 16
#define NPART (B * CHUNKS)                   // 1024 CTA-level partials

// Scratch for CTA partials + per-batch arrival counters (allocation-free).
// g_count is statically zero-initialized; the last CTA of each batch resets
// its counter to 0, so every graph replay starts from the same state.
__device__ float g_pm[NPART];
__device__ float g_pl[NPART];
__device__ float g_pacc[(size_t)NPART * H];   // 3.1 MB (stays L2-hot: hidden
                                              // is read with streaming hints)
__device__ unsigned int g_count[B] = {};

// ---------------------------------------------------------------------------
// Single fused kernel: one-pass online softmax + weighted accumulate, with
// CTA-level merge through shared memory and a last-CTA-per-batch combine.
// ---------------------------------------------------------------------------
__global__ __launch_bounds__(256, 2)
void attn_fused(const float* __restrict__ hidden, const float* __restrict__ q,
                float* __restrict__ out)
{
    const int bx    = blockIdx.x;            // 0..1023
    const int b     = bx / CHUNKS;           // batch
    const int chunk = bx % CHUNKS;
    const int wid   = threadIdx.x >> 5;
    const int lane  = threadIdx.x & 31;

    const float4* qv4 = (const float4*)q;
    float4 qv[6];
#pragma unroll
    for (int i = 0; i < 6; i++) qv[i] = qv4[i * 32 + lane];

    const float* base = hidden + (size_t)b * S * H;
    const int row0 = chunk * (S / CHUNKS) + wid * ROWS_PER_WARP;

    float4 acc[6];
#pragma unroll
    for (int i = 0; i < 6; i++) acc[i] = make_float4(0.f, 0.f, 0.f, 0.f);
    float m = -INFINITY;
    float l = 0.f;

    // prefetch first row (streaming loads: single-use 384 MB stream must not
    // evict the partial buffer from L2)
    float4 x[6], xn[6];
    {
        const float4* rp = (const float4*)(base + (size_t)row0 * H);
#pragma unroll
        for (int i = 0; i < 6; i++) x[i] = __ldcs(&rp[i * 32 + lane]);
    }

    for (int r = 0; r < ROWS_PER_WARP; r++) {
        // prefetch next row (independent of the softmax chain below)
        if (r + 1 < ROWS_PER_WARP) {
            const float4* rp = (const float4*)(base + (size_t)(row0 + r + 1) * H);
#pragma unroll
            for (int i = 0; i < 6; i++) xn[i] = __ldcs(&rp[i * 32 + lane]);
        }

        // dot(hidden_row, q)
        float d = 0.f;
#pragma unroll
        for (int i = 0; i < 6; i++) {
            d = fmaf(x[i].x, qv[i].x, d);
            d = fmaf(x[i].y, qv[i].y, d);
            d = fmaf(x[i].z, qv[i].z, d);
            d = fmaf(x[i].w, qv[i].w, d);
        }
#pragma unroll
        for (int o = 16; o > 0; o >>= 1)
            d += __shfl_xor_sync(0xffffffffu, d, o);

        // online softmax update (warp-uniform m, l)
        if (d > m) {
            const float sc = __expf(m - d);   // exp(-inf) = 0 on first row
            l *= sc;
#pragma unroll
            for (int i = 0; i < 6; i++) {
                acc[i].x *= sc; acc[i].y *= sc; acc[i].z *= sc; acc[i].w *= sc;
            }
            m = d;
        }
        const float w = __expf(d - m);
        l += w;
#pragma unroll
        for (int i = 0; i < 6; i++) {
            acc[i].x = fmaf(w, x[i].x, acc[i].x);
            acc[i].y = fmaf(w, x[i].y, acc[i].y);
            acc[i].z = fmaf(w, x[i].z, acc[i].z);
            acc[i].w = fmaf(w, x[i].w, acc[i].w);
        }

#pragma unroll
        for (int i = 0; i < 6; i++) x[i] = xn[i];
    }

    // ---- CTA-level merge of the 8 warp partials through shared memory ----
    __shared__ float s_m[WARPS];
    __shared__ float s_l[WARPS];
    __shared__ float s_acc[WARPS][H];        // 24 KB

    if (lane == 0) { s_m[wid] = m; s_l[wid] = l; }
    {
        float4* sa = (float4*)s_acc[wid];
#pragma unroll
        for (int i = 0; i < 6; i++) sa[i * 32 + lane] = acc[i];
    }
    __syncthreads();

    float M = s_m[0];
#pragma unroll
    for (int w = 1; w < WARPS; w++) M = fmaxf(M, s_m[w]);

    // each thread owns 3 h-values (768 / 256); consecutive threads ->
    // consecutive smem addresses (conflict-free) and coalesced STG
    float* pa = g_pacc + (size_t)bx * H;
#pragma unroll
    for (int j = 0; j < 3; j++) {
        const int h = threadIdx.x + j * 256;
        float r = 0.f;
#pragma unroll
        for (int w = 0; w < WARPS; w++)
            r = fmaf(__expf(s_m[w] - M), s_acc[w][h], r);
        pa[h] = r;
    }
    if (threadIdx.x == 0) {
        float L = 0.f;
#pragma unroll
        for (int w = 0; w < WARPS; w++) L = fmaf(__expf(s_m[w] - M), s_l[w], L);
        g_pm[bx] = M;
        g_pl[bx] = L;
    }

    // ---- last CTA of this batch combines the 32 partials ----
    __shared__ unsigned int s_ticket;
    if (threadIdx.x == 0) {
        __threadfence();                       // partials visible before count
        s_ticket = atomicAdd(&g_count[b], 1u);
    }
    __syncthreads();
    if (s_ticket != CHUNKS - 1) return;

    __threadfence();                           // acquire: see all partials

    const int p0 = b * CHUNKS;
    float GM = -INFINITY;
#pragma unroll
    for (int c = 0; c < CHUNKS; c++) GM = fmaxf(GM, g_pm[p0 + c]);

    // 256 threads x 3 h-values; partial reads are L2-hot (96 KB per batch)
    float r0 = 0.f, r1 = 0.f, r2 = 0.f, L = 0.f;
    const int h0 = threadIdx.x;
#pragma unroll 4
    for (int c = 0; c < CHUNKS; c++) {
        const float w = __expf(g_pm[p0 + c] - GM);
        const float* pc = g_pacc + (size_t)(p0 + c) * H;
        L  = fmaf(w, g_pl[p0 + c], L);
        r0 = fmaf(w, pc[h0],       r0);
        r1 = fmaf(w, pc[h0 + 256], r1);
        r2 = fmaf(w, pc[h0 + 512], r2);
    }
    const float invL = 1.f / L;
    float* ob = out + b * H;
    ob[h0]       = r0 * invL;
    ob[h0 + 256] = r1 * invL;
    ob[h0 + 512] = r2 * invL;

    if (threadIdx.x == 0) g_count[b] = 0;      // reset for next graph replay
}

extern "C" void kernel_launch(void* const* d_in, const int* in_sizes, int n_in,
                              void* d_out, int out_size)
{
    const float* hidden = (const float*)d_in[0];   // [32, 4096, 768] f32
    const float* querys = (const float*)d_in[1];   // [1, 768] f32
    float* out = (float*)d_out;                    // [32, 768] f32

    attn_fused<<<B * CHUNKS, 256>>>(hidden, querys, out);
}